// round 10
// baseline (speedup 1.0000x reference)
#include <cuda_runtime.h>
#include <cuda_bf16.h>

#define FULL 0xffffffffu

namespace {
constexpr int NB   = 32;
constexpr int NP   = 32;
constexpr int DD   = 12;
constexpr int PP   = 32;
constexpr int LL   = 1024;
constexpr int LOUT = 32;
constexpr int CPL  = 8;            // cols per lane
constexpr int CP2  = CPL / 2;      // packed f32x2 pairs per lane
constexpr int WBLK = 32 * CPL;     // 256 cols per warp
constexpr int NBLK = LL / WBLK;    // 4 warps per (b,n)
constexpr float BIGV = 1e30f;
}

typedef unsigned long long u64;

// Blackwell packed fp32x2 ops (FFMA2/FADD2 in SASS — only reachable via PTX).
__device__ __forceinline__ u64 pack2(float lo, float hi) {
    u64 r; asm("mov.b64 %0, {%1, %2};" : "=l"(r) : "f"(lo), "f"(hi)); return r;
}
__device__ __forceinline__ void unpack2(u64 v, float& lo, float& hi) {
    asm("mov.b64 {%0, %1}, %2;" : "=f"(lo), "=f"(hi) : "l"(v));
}
__device__ __forceinline__ u64 ffma2(u64 a, u64 b, u64 c) {
    u64 d; asm("fma.rn.f32x2 %0, %1, %2, %3;" : "=l"(d) : "l"(a), "l"(b), "l"(c)); return d;
}
__device__ __forceinline__ u64 fadd2(u64 a, u64 b) {
    u64 d; asm("add.rn.f32x2 %0, %1, %2;" : "=l"(d) : "l"(a), "l"(b)); return d;
}

// One CTA (4 warps) per (b, n); warp w owns column block w (256 cols).
// NO barriers in the main loop: the single float that crosses warps per row
// (D[i][block-last-col]) is passed as a tagged 64-bit word {tag=i+1, value}
// via st.release.cta / ld.acquire.cta on aligned smem (single-copy atomic,
// properly ordered — unlike the R4 volatile version, which raced). Warps are
// fully decoupled; warp 0 never waits, steady-state skew is ~1 row.
//
// Row recurrence (w == 1 exactly, RHO = 1.0):
//   cur[j] = c[j] + min(m[j], cur[j-1]),  m[j] = min(D[i-1,j-1], D[i-1,j])
// as composition of affine-min maps f_j(v) = min(beta_j, v + alpha_j),
// (f2 o f1) = (alpha1+alpha2, min(beta2, beta1+alpha2)): one composite
// Kogge-Stone scan (5 hops). Cost row uses packed f32x2 FMAs, two
// independent accumulator chains per pair (dep depth 6, not 12).
__global__ void __launch_bounds__(128, 3)
dtw_fused_kernel(const float* __restrict__ x,
                 const float* __restrict__ patts,
                 float* __restrict__ out)
{
    const int gid  = blockIdx.x;        // 0..1023
    const int b    = gid >> 5;
    const int n    = gid & 31;
    const int w    = threadIdx.x >> 5;  // column block 0..3
    const int lane = threadIdx.x & 31;

    __shared__ alignas(8) u64 hand[NBLK - 1][PP];   // {tag=i+1 (hi), value (lo)}

    // zero all tags, then one (and only) CTA barrier
    for (int idx = threadIdx.x; idx < (NBLK - 1) * PP; idx += 128)
        ((u64*)hand)[idx] = 0ull;
    __syncthreads();

    // lane holds patts[n][d][lane]; store -2*p for the FMA form of sqdist.
    float prow[DD];
    float p2 = 0.0f;
    {
        const float* pp = patts + n * (DD * PP) + lane;
        #pragma unroll
        for (int d = 0; d < DD; ++d) {
            float v = pp[d * PP];
            p2 = fmaf(v, v, p2);
            prow[d] = -2.0f * v;
        }
    }

    // x chunk for this warp's column block (packed f32x2), reused by all rows.
    const float* xb = x + b * (DD * LL);
    const int j0 = w * WBLK;
    u64 xp[DD][CP2];
    u64 px2[CP2];
    {
        u64 z = pack2(0.0f, 0.0f);
        #pragma unroll
        for (int k2 = 0; k2 < CP2; ++k2) px2[k2] = z;
    }
    #pragma unroll
    for (int d = 0; d < DD; ++d) {
        const float* px = xb + d * LL + j0 + CPL * lane;
        float4 v0 = *reinterpret_cast<const float4*>(px);
        float4 v1 = *reinterpret_cast<const float4*>(px + 4);
        xp[d][0] = pack2(v0.x, v0.y);
        xp[d][1] = pack2(v0.z, v0.w);
        xp[d][2] = pack2(v1.x, v1.y);
        xp[d][3] = pack2(v1.z, v1.w);
        #pragma unroll
        for (int k2 = 0; k2 < CP2; ++k2)
            px2[k2] = ffma2(xp[d][k2], xp[d][k2], px2[k2]);
    }

    float* outb = out + ((b * NP + n) * PP) * LOUT;
    float Dp[CPL];      // previous DP row for this warp's block
    float bm = BIGV;    // D[i-1][j0-1]; for w>0 it's the previous row's bl

    #pragma unroll 1
    for (int i = 0; i < PP; ++i) {
        // ---- cost row c[k] (alpha), packed f32x2, two accumulator chains ----
        float p2b = __shfl_sync(FULL, p2, i);
        u64 p2b2 = pack2(p2b, p2b);
        u64 cc[CP2], cd[CP2];
        #pragma unroll
        for (int k2 = 0; k2 < CP2; ++k2) {
            cc[k2] = fadd2(p2b2, px2[k2]);    // chain 0 seeded with p2 + x2
            cd[k2] = pack2(0.0f, 0.0f);       // chain 1
        }
        #pragma unroll
        for (int d = 0; d < DD; d += 2) {
            float pb0 = __shfl_sync(FULL, prow[d], i);
            float pb1 = __shfl_sync(FULL, prow[d + 1], i);
            u64 pa = pack2(pb0, pb0);
            u64 pbp = pack2(pb1, pb1);
            #pragma unroll
            for (int k2 = 0; k2 < CP2; ++k2) {
                cc[k2] = ffma2(pa,  xp[d][k2],     cc[k2]);
                cd[k2] = ffma2(pbp, xp[d + 1][k2], cd[k2]);
            }
        }
        float c[CPL];
        #pragma unroll
        for (int k2 = 0; k2 < CP2; ++k2) {
            u64 s = fadd2(cc[k2], cd[k2]);
            unpack2(s, c[2 * k2], c[2 * k2 + 1]);
        }

        // ---- left-boundary carry for this row (acquire handoff) ----
        float bl;
        if (w == 0) {
            bl = (i == 0) ? 0.0f : BIGV;   // D[0,0] seed enters as v
        } else {
            const unsigned tag = (unsigned)(i + 1);
            const u64* hp = &hand[w - 1][i];
            u64 v;
            asm volatile("ld.acquire.cta.b64 %0, [%1];" : "=l"(v) : "l"(hp) : "memory");
            while ((unsigned)(v >> 32) != tag) {
                __nanosleep(20);
                asm volatile("ld.acquire.cta.b64 %0, [%1];" : "=l"(v) : "l"(hp) : "memory");
            }
            bl = __uint_as_float((unsigned)v);
        }

        // ---- local inclusive composites (A = prefix sum of c, B = bound) ----
        float A[CPL], Bv[CPL];
        float shin = __shfl_up_sync(FULL, Dp[CPL - 1], 1);
        if (i == 0) {
            A[0] = c[0]; Bv[0] = BIGV;
            #pragma unroll
            for (int k = 1; k < CPL; ++k) { A[k] = A[k - 1] + c[k]; Bv[k] = BIGV; }
        } else {
            float m0 = fminf((lane == 0) ? bm : shin, Dp[0]);
            A[0]  = c[0];
            Bv[0] = c[0] + m0;
            #pragma unroll
            for (int k = 1; k < CPL; ++k) {
                float mk = fminf(Dp[k - 1], Dp[k]);
                A[k]  = A[k - 1] + c[k];
                Bv[k] = fminf(c[k] + mk, Bv[k - 1] + c[k]);
            }
        }

        // ---- single composite warp scan over lane maps ----
        float Aw = A[CPL - 1], Bw = Bv[CPL - 1];
        #pragma unroll
        for (int o = 1; o < 32; o <<= 1) {
            float Au = __shfl_up_sync(FULL, Aw, o);
            float Bu = __shfl_up_sync(FULL, Bw, o);
            if (lane >= o) {
                Bw = fminf(Bw, Bu + Aw);  // uses pre-update Aw
                Aw = Aw + Au;
            }
        }
        float Ae = __shfl_up_sync(FULL, Aw, 1);
        float Be = __shfl_up_sync(FULL, Bw, 1);
        float vin = (lane == 0) ? bl : fminf(Be, bl + Ae);

        // ---- outputs: cur[k] = min(B[k], vin + A[k]) ----
        float cur[CPL];
        #pragma unroll
        for (int k = 0; k < CPL; ++k)
            cur[k] = fminf(Bv[k], vin + A[k]);

        // ---- publish carry for the warp to the right (release handoff) ----
        if (w < NBLK - 1 && lane == 31) {
            u64 pk = (((u64)(unsigned)(i + 1)) << 32) |
                     (u64)__float_as_uint(cur[CPL - 1]);
            const u64* hp = &hand[w][i];
            asm volatile("st.release.cta.b64 [%0], %1;" :: "l"(hp), "l"(pk) : "memory");
        }

        // ---- output: cols 992..1023 = lanes 28..31 of last warp ----
        if (w == NBLK - 1 && lane >= 28) {
            float* po = outb + i * LOUT + (lane - 28) * CPL;
            *reinterpret_cast<float4*>(po)     = make_float4(cur[0], cur[1], cur[2], cur[3]);
            *reinterpret_cast<float4*>(po + 4) = make_float4(cur[4], cur[5], cur[6], cur[7]);
        }

        bm = bl;   // valid as D[i-1][j0-1] only for w>0; w==0 never reads it
                   // (w==0 uses the (lane==0)?bm path only when i>0, where bm
                   //  must be BIGV: bl for w==0,i>0 is BIGV, so bm stays BIGV)
        #pragma unroll
        for (int k = 0; k < CPL; ++k) Dp[k] = cur[k];
    }
}

extern "C" void kernel_launch(void* const* d_in, const int* in_sizes, int n_in,
                              void* d_out, int out_size) {
    const float* x     = (const float*)d_in[0];   // [32, 12, 1024]
    const float* patts = (const float*)d_in[1];   // [32, 12, 32]
    float* out = (float*)d_out;                   // [32, 32, 32, 32]
    (void)in_sizes; (void)n_in; (void)out_size;
    dtw_fused_kernel<<<NB * NP, 128>>>(x, patts, out);
}

// round 11
// speedup vs baseline: 1.0044x; 1.0044x over previous
#include <cuda_runtime.h>
#include <cuda_bf16.h>

#define FULL 0xffffffffu

namespace {
constexpr int NB   = 32;
constexpr int NP   = 32;
constexpr int DD   = 12;
constexpr int PP   = 32;
constexpr int LL   = 1024;
constexpr int LOUT = 32;
constexpr int CPL  = 8;            // cols per lane
constexpr int CP2  = CPL / 2;      // packed f32x2 pairs per lane
constexpr int WBLK = 32 * CPL;     // 256 cols per warp
constexpr int NBLK = LL / WBLK;    // 4 warps per (b,n)
constexpr float BIGV = 1e30f;
}

typedef unsigned long long u64;

// Blackwell packed fp32x2 ops (FFMA2/FADD2 in SASS — only reachable via PTX).
__device__ __forceinline__ u64 pack2(float lo, float hi) {
    u64 r; asm("mov.b64 %0, {%1, %2};" : "=l"(r) : "f"(lo), "f"(hi)); return r;
}
__device__ __forceinline__ void unpack2(u64 v, float& lo, float& hi) {
    asm("mov.b64 {%0, %1}, %2;" : "=f"(lo), "=f"(hi) : "l"(v));
}
__device__ __forceinline__ u64 ffma2(u64 a, u64 b, u64 c) {
    u64 d; asm("fma.rn.f32x2 %0, %1, %2, %3;" : "=l"(d) : "l"(a), "l"(b), "l"(c)); return d;
}
__device__ __forceinline__ u64 fadd2(u64 a, u64 b) {
    u64 d; asm("add.rn.f32x2 %0, %1, %2;" : "=l"(d) : "l"(a), "l"(b)); return d;
}

// One CTA (4 warps) per (b, n); warp w owns column block w (256 cols).
// Barrier-free mainloop: the single float crossing warps per row
// (D[i][block-last-col]) is a tagged 64-bit {tag=i+1, value} passed via
// st.release.cta / ld.acquire.cta on aligned smem. Warps fully decouple;
// warp 0 never waits, steady-state skew ~1 row.
//
// Correctness note (the R4/R5/R10 bug): for w==0, the up-left boundary
// D[i-1][-1] is ALWAYS +inf; carrying forward bl would leak the 0.0 seed from
// i==0 into i==1. Hence bm = (w==0) ? BIGV : bl.
//
// Row recurrence (w == 1 exactly, RHO = 1.0):
//   cur[j] = c[j] + min(m[j], cur[j-1]),  m[j] = min(D[i-1,j-1], D[i-1,j])
// as composition of affine-min maps f_j(v) = min(beta_j, v + alpha_j),
// (f2 o f1) = (alpha1+alpha2, min(beta2, beta1+alpha2)): one composite
// Kogge-Stone scan (5 hops). Software pipeline: row i+1's packed cost FMAs
// are issued in the same iteration as row i's scan/spin, filling the stalls.
__global__ void __launch_bounds__(128, 3)
dtw_fused_kernel(const float* __restrict__ x,
                 const float* __restrict__ patts,
                 float* __restrict__ out)
{
    const int gid  = blockIdx.x;        // 0..1023
    const int b    = gid >> 5;
    const int n    = gid & 31;
    const int w    = threadIdx.x >> 5;  // column block 0..3
    const int lane = threadIdx.x & 31;

    __shared__ alignas(8) u64 hand[NBLK - 1][PP];   // {tag=i+1 (hi), value (lo)}

    // zero all tags, then the single CTA barrier of the kernel
    for (int idx = threadIdx.x; idx < (NBLK - 1) * PP; idx += 128)
        ((u64*)hand)[idx] = 0ull;
    __syncthreads();

    // lane holds patts[n][d][lane]; store -2*p for the FMA form of sqdist.
    float prow[DD];
    float p2 = 0.0f;
    {
        const float* pp = patts + n * (DD * PP) + lane;
        #pragma unroll
        for (int d = 0; d < DD; ++d) {
            float v = pp[d * PP];
            p2 = fmaf(v, v, p2);
            prow[d] = -2.0f * v;
        }
    }

    // x chunk for this warp's column block (packed f32x2), reused by all rows.
    const float* xb = x + b * (DD * LL);
    const int j0 = w * WBLK;
    u64 xp[DD][CP2];
    u64 px2[CP2];
    {
        u64 z = pack2(0.0f, 0.0f);
        #pragma unroll
        for (int k2 = 0; k2 < CP2; ++k2) px2[k2] = z;
    }
    #pragma unroll
    for (int d = 0; d < DD; ++d) {
        const float* px = xb + d * LL + j0 + CPL * lane;
        float4 v0 = *reinterpret_cast<const float4*>(px);
        float4 v1 = *reinterpret_cast<const float4*>(px + 4);
        xp[d][0] = pack2(v0.x, v0.y);
        xp[d][1] = pack2(v0.z, v0.w);
        xp[d][2] = pack2(v1.x, v1.y);
        xp[d][3] = pack2(v1.z, v1.w);
        #pragma unroll
        for (int k2 = 0; k2 < CP2; ++k2)
            px2[k2] = ffma2(xp[d][k2], xp[d][k2], px2[k2]);
    }

    // packed cost row i: cc[k2] = (p2 + x2) + sum_d (-2 p_d) * x_d
    auto costrow = [&](int i, u64 cc[CP2]) {
        float p2b = __shfl_sync(FULL, p2, i);
        u64 p2b2 = pack2(p2b, p2b);
        #pragma unroll
        for (int k2 = 0; k2 < CP2; ++k2) cc[k2] = fadd2(p2b2, px2[k2]);
        #pragma unroll
        for (int d = 0; d < DD; ++d) {
            float pb = __shfl_sync(FULL, prow[d], i);
            u64 pbb = pack2(pb, pb);
            #pragma unroll
            for (int k2 = 0; k2 < CP2; ++k2)
                cc[k2] = ffma2(pbb, xp[d][k2], cc[k2]);
        }
    };

    float* outb = out + ((b * NP + n) * PP) * LOUT;
    float Dp[CPL];      // previous DP row for this warp's block
    float bm = BIGV;    // D[i-1][j0-1]; meaningful only for w>0

    u64 cC[CP2];        // pipelined: packed cost of the current row
    costrow(0, cC);

    #pragma unroll 1
    for (int i = 0; i < PP; ++i) {
        // ---- pipelined: issue next row's cost FMAs (independent work) ----
        u64 cN[CP2];
        if (i + 1 < PP) costrow(i + 1, cN);

        float c[CPL];
        #pragma unroll
        for (int k2 = 0; k2 < CP2; ++k2)
            unpack2(cC[k2], c[2 * k2], c[2 * k2 + 1]);

        // ---- left-boundary carry for this row (acquire handoff) ----
        float bl;
        if (w == 0) {
            bl = (i == 0) ? 0.0f : BIGV;   // D[0,0] seed enters as v
        } else {
            const unsigned tag = (unsigned)(i + 1);
            const u64* hp = &hand[w - 1][i];
            u64 v;
            asm volatile("ld.acquire.cta.b64 %0, [%1];" : "=l"(v) : "l"(hp) : "memory");
            while ((unsigned)(v >> 32) != tag) {
                asm volatile("ld.acquire.cta.b64 %0, [%1];" : "=l"(v) : "l"(hp) : "memory");
            }
            bl = __uint_as_float((unsigned)v);
        }

        // ---- local inclusive composites (A = prefix sum of c, B = bound) ----
        float A[CPL], Bv[CPL];
        float shin = __shfl_up_sync(FULL, Dp[CPL - 1], 1);
        if (i == 0) {
            A[0] = c[0]; Bv[0] = BIGV;
            #pragma unroll
            for (int k = 1; k < CPL; ++k) { A[k] = A[k - 1] + c[k]; Bv[k] = BIGV; }
        } else {
            float m0 = fminf((lane == 0) ? bm : shin, Dp[0]);
            A[0]  = c[0];
            Bv[0] = c[0] + m0;
            #pragma unroll
            for (int k = 1; k < CPL; ++k) {
                float mk = fminf(Dp[k - 1], Dp[k]);
                A[k]  = A[k - 1] + c[k];
                Bv[k] = fminf(c[k] + mk, Bv[k - 1] + c[k]);
            }
        }

        // ---- single composite warp scan over lane maps ----
        float Aw = A[CPL - 1], Bw = Bv[CPL - 1];
        #pragma unroll
        for (int o = 1; o < 32; o <<= 1) {
            float Au = __shfl_up_sync(FULL, Aw, o);
            float Bu = __shfl_up_sync(FULL, Bw, o);
            if (lane >= o) {
                Bw = fminf(Bw, Bu + Aw);  // uses pre-update Aw
                Aw = Aw + Au;
            }
        }
        float Ae = __shfl_up_sync(FULL, Aw, 1);
        float Be = __shfl_up_sync(FULL, Bw, 1);
        float vin = (lane == 0) ? bl : fminf(Be, bl + Ae);

        // ---- outputs: cur[k] = min(B[k], vin + A[k]) ----
        float cur[CPL];
        #pragma unroll
        for (int k = 0; k < CPL; ++k)
            cur[k] = fminf(Bv[k], vin + A[k]);

        // ---- publish carry for the warp to the right (release handoff) ----
        if (w < NBLK - 1 && lane == 31) {
            u64 pk = (((u64)(unsigned)(i + 1)) << 32) |
                     (u64)__float_as_uint(cur[CPL - 1]);
            const u64* hp = &hand[w][i];
            asm volatile("st.release.cta.b64 [%0], %1;" :: "l"(hp), "l"(pk) : "memory");
        }

        // ---- output: cols 992..1023 = lanes 28..31 of last warp ----
        if (w == NBLK - 1 && lane >= 28) {
            float* po = outb + i * LOUT + (lane - 28) * CPL;
            *reinterpret_cast<float4*>(po)     = make_float4(cur[0], cur[1], cur[2], cur[3]);
            *reinterpret_cast<float4*>(po + 4) = make_float4(cur[4], cur[5], cur[6], cur[7]);
        }

        // D[i-1][-1] is ALWAYS +inf for w==0 (never carry the seed forward).
        bm = (w == 0) ? BIGV : bl;
        #pragma unroll
        for (int k = 0; k < CPL; ++k) Dp[k] = cur[k];
        #pragma unroll
        for (int k2 = 0; k2 < CP2; ++k2) cC[k2] = cN[k2];
    }
}

extern "C" void kernel_launch(void* const* d_in, const int* in_sizes, int n_in,
                              void* d_out, int out_size) {
    const float* x     = (const float*)d_in[0];   // [32, 12, 1024]
    const float* patts = (const float*)d_in[1];   // [32, 12, 32]
    float* out = (float*)d_out;                   // [32, 32, 32, 32]
    (void)in_sizes; (void)n_in; (void)out_size;
    dtw_fused_kernel<<<NB * NP, 128>>>(x, patts, out);
}